// round 13
// baseline (speedup 1.0000x reference)
#include <cuda_runtime.h>
#include <math.h>

#define B    64
#define H    1024
#define NH   8
#define HD   128
#define SQ   24
#define NE   512
#define K3H  3072
#define H4   4096

#define LOGITS_TOT (SQ*B*NE)   // 786432
#define IDX_TOT    (SQ*B*3)    // 4608

#define KS_GATES 16
#define KS_QKV   16
#define KS_SMALL 32

typedef unsigned long long ull;

// ---------------- persistent device scratch (no allocations allowed) ----------------
__device__ float d_Wcat[(size_t)H4 * H4];     // [4096][4096] = W_ih | W_hh packed
__device__ float d_Xcat[(size_t)B * H4];      // [64][4096]  = x(3072) | h(1024)
__device__ float d_c[(size_t)B * H];
__device__ float d_gatesp[KS_GATES * (size_t)B * H4];
__device__ float d_qkvp[KS_QKV * (size_t)B * K3H];
__device__ float d_Kc[(size_t)SQ * B * H];
__device__ float d_Vc[(size_t)SQ * B * H];
__device__ float d_ctx[(size_t)B * H];
__device__ float d_aop[KS_SMALL * (size_t)B * H];
__device__ float d_qin[(size_t)B * H];
__device__ float d_qp[KS_SMALL * (size_t)B * H];

// ---------------- packed f32x2 helpers ----------------
__device__ __forceinline__ ull pk2(float x, float y) {
    ull r;
    asm("mov.b64 %0, {%1,%2};" : "=l"(r) : "f"(x), "f"(y));
    return r;
}
__device__ __forceinline__ void fma2(ull& d, ull a, ull b) {
    asm("fma.rn.f32x2 %0, %1, %2, %3;" : "=l"(d) : "l"(a), "l"(b), "l"(d));
}
__device__ __forceinline__ float2 up2(ull v) {
    float2 r;
    asm("mov.b64 {%0,%1}, %2;" : "=f"(r.x), "=f"(r.y) : "l"(v));
    return r;
}
__device__ __forceinline__ void add4(float4& a, float4 b) {
    a.x += b.x; a.y += b.y; a.z += b.z; a.w += b.w;
}

// ---------------- init kernels ----------------
__global__ void init_wcat(const float* __restrict__ W_ih, const float* __restrict__ W_hh) {
    size_t id = (size_t)blockIdx.x * 256 + threadIdx.x;
    int j = (int)(id >> 12);
    int k = (int)(id & 4095);
    d_Wcat[id] = (k < K3H) ? W_ih[(size_t)j * K3H + k]
                           : W_hh[(size_t)j * H + (k - K3H)];
}

__global__ void init_state(const float* __restrict__ hidden,
                           const float* __restrict__ cell,
                           const float* __restrict__ init_in) {
    int id = blockIdx.x * 256 + threadIdx.x;
    int b = id >> 12;
    int k = id & 4095;
    if (k < K3H) {
        d_Xcat[id] = init_in[(size_t)b * K3H + k];
    } else {
        d_Xcat[id] = hidden[(size_t)b * H + (k - K3H)];
        d_c[(size_t)b * H + (k - K3H)] = cell[(size_t)b * H + (k - K3H)];
    }
}

// ---------------- fp32 GEMM with packed FFMA2 (R7-proven, unchanged) ----------------
__global__ __launch_bounds__(128)
void gemm64(const float* __restrict__ A, int lda,
            const float* __restrict__ W, int K, int N,
            float* __restrict__ C, int kper)
{
    __shared__ __align__(16) float As[2][16][72];
    __shared__ __align__(16) float Ws[2][16][260];

    const int tx = threadIdx.x;
    const int tm = tx >> 4;
    const int tn = tx & 15;
    const int nblk = blockIdx.x * 256;
    const int k0 = blockIdx.y * kper;

    const int ldRow = tx >> 2;
    const int ldKg  = tx & 3;

    const float* Aptr = A + (size_t)ldRow * lda + k0 + ldKg * 4;
    const float* Wptr = W + (size_t)(nblk + ldRow) * K + k0 + ldKg * 4;

    ull acc[8][8];
#pragma unroll
    for (int i = 0; i < 8; i++)
#pragma unroll
        for (int j = 0; j < 8; j++) acc[i][j] = 0ull;

    const int nk = kper / 16;

    {
#pragma unroll
        for (int i = 0; i < 2; i++) {
            float4 v = *reinterpret_cast<const float4*>(Aptr + (size_t)i * 32 * lda);
            int row = ldRow + i * 32;
            As[0][ldKg * 4 + 0][row] = v.x; As[0][ldKg * 4 + 1][row] = v.y;
            As[0][ldKg * 4 + 2][row] = v.z; As[0][ldKg * 4 + 3][row] = v.w;
        }
#pragma unroll
        for (int i = 0; i < 8; i++) {
            float4 v = *reinterpret_cast<const float4*>(Wptr + (size_t)i * 32 * K);
            int row = ldRow + i * 32;
            Ws[0][ldKg * 4 + 0][row] = v.x; Ws[0][ldKg * 4 + 1][row] = v.y;
            Ws[0][ldKg * 4 + 2][row] = v.z; Ws[0][ldKg * 4 + 3][row] = v.w;
        }
    }
    __syncthreads();

    for (int it = 0; it < nk; it++) {
        const int st = it & 1;
        float4 va[2], vw[8];
        if (it + 1 < nk) {
            const int koff = (it + 1) * 16;
#pragma unroll
            for (int i = 0; i < 2; i++)
                va[i] = *reinterpret_cast<const float4*>(Aptr + (size_t)i * 32 * lda + koff);
#pragma unroll
            for (int i = 0; i < 8; i++)
                vw[i] = *reinterpret_cast<const float4*>(Wptr + (size_t)i * 32 * K + koff);
        }
#pragma unroll
        for (int kk = 0; kk < 16; kk++) {
            float a[8];
            *reinterpret_cast<float4*>(&a[0]) = *reinterpret_cast<const float4*>(&As[st][kk][tm * 8]);
            *reinterpret_cast<float4*>(&a[4]) = *reinterpret_cast<const float4*>(&As[st][kk][tm * 8 + 4]);
            ull ap[8];
#pragma unroll
            for (int i = 0; i < 8; i++) ap[i] = pk2(a[i], a[i]);
#pragma unroll
            for (int q = 0; q < 4; q++) {
                const ull* bp = reinterpret_cast<const ull*>(&Ws[st][kk][q * 64 + tn * 4]);
                ull b0 = bp[0], b1 = bp[1];
#pragma unroll
                for (int i = 0; i < 8; i++) {
                    fma2(acc[i][q * 2 + 0], ap[i], b0);
                    fma2(acc[i][q * 2 + 1], ap[i], b1);
                }
            }
        }
        if (it + 1 < nk) {
            const int sn = st ^ 1;
#pragma unroll
            for (int i = 0; i < 2; i++) {
                int row = ldRow + i * 32;
                As[sn][ldKg * 4 + 0][row] = va[i].x; As[sn][ldKg * 4 + 1][row] = va[i].y;
                As[sn][ldKg * 4 + 2][row] = va[i].z; As[sn][ldKg * 4 + 3][row] = va[i].w;
            }
#pragma unroll
            for (int i = 0; i < 8; i++) {
                int row = ldRow + i * 32;
                Ws[sn][ldKg * 4 + 0][row] = vw[i].x; Ws[sn][ldKg * 4 + 1][row] = vw[i].y;
                Ws[sn][ldKg * 4 + 2][row] = vw[i].z; Ws[sn][ldKg * 4 + 3][row] = vw[i].w;
            }
        }
        __syncthreads();
    }

    float* Cp = C + (size_t)blockIdx.y * B * N;
#pragma unroll
    for (int i = 0; i < 8; i++) {
        const size_t rbase = (size_t)(tm * 8 + i) * N + nblk;
#pragma unroll
        for (int q = 0; q < 4; q++) {
            float2 lo = up2(acc[i][q * 2 + 0]);
            float2 hi = up2(acc[i][q * 2 + 1]);
            float4 v = make_float4(lo.x, lo.y, hi.x, hi.y);
            *reinterpret_cast<float4*>(&Cp[rbase + q * 64 + tn * 4]) = v;
        }
    }
}

// ---------------- reductions ----------------
__device__ __forceinline__ float sigmoidf_(float x) { return 1.f / (1.f + expf(-x)); }

// 256 blocks x 256 threads; thread = (output float4, s-group). 64 outputs/block. (R12-proven)
__global__ __launch_bounds__(256)
void lstm_update(const float* __restrict__ b_ih, const float* __restrict__ b_hh) {
    __shared__ __align__(16) float4 red[64][4][4];
    int tid = blockIdx.x * 256 + threadIdx.x;
    int outIdx = tid >> 2;
    int sg = tid & 3;
    int b = outIdx >> 8;
    int j4 = (outIdx & 255) * 4;
    size_t base = (size_t)b * H4;

    float4 gi, gf, gg, go;
    if (sg == 0) {
        gi = *reinterpret_cast<const float4*>(&b_ih[j4]);
        gf = *reinterpret_cast<const float4*>(&b_ih[1024 + j4]);
        gg = *reinterpret_cast<const float4*>(&b_ih[2048 + j4]);
        go = *reinterpret_cast<const float4*>(&b_ih[3072 + j4]);
        add4(gi, *reinterpret_cast<const float4*>(&b_hh[j4]));
        add4(gf, *reinterpret_cast<const float4*>(&b_hh[1024 + j4]));
        add4(gg, *reinterpret_cast<const float4*>(&b_hh[2048 + j4]));
        add4(go, *reinterpret_cast<const float4*>(&b_hh[3072 + j4]));
    } else {
        gi = gf = gg = go = make_float4(0.f, 0.f, 0.f, 0.f);
    }
#pragma unroll
    for (int s = 0; s < 4; s++) {
        const float* g = d_gatesp + (size_t)(sg * 4 + s) * B * H4 + base;
        add4(gi, *reinterpret_cast<const float4*>(&g[j4]));
        add4(gf, *reinterpret_cast<const float4*>(&g[1024 + j4]));
        add4(gg, *reinterpret_cast<const float4*>(&g[2048 + j4]));
        add4(go, *reinterpret_cast<const float4*>(&g[3072 + j4]));
    }
    int lo = threadIdx.x >> 2;
    red[lo][0][sg] = gi; red[lo][1][sg] = gf;
    red[lo][2][sg] = gg; red[lo][3][sg] = go;
    __syncthreads();

    if (threadIdx.x < 64) {
        int o = blockIdx.x * 64 + threadIdx.x;
        int bb = o >> 8;
        int jj4 = (o & 255) * 4;
        float4 Gi = red[threadIdx.x][0][0], Gf = red[threadIdx.x][1][0];
        float4 Gg = red[threadIdx.x][2][0], Go = red[threadIdx.x][3][0];
#pragma unroll
        for (int s = 1; s < 4; s++) {
            add4(Gi, red[threadIdx.x][0][s]); add4(Gf, red[threadIdx.x][1][s]);
            add4(Gg, red[threadIdx.x][2][s]); add4(Go, red[threadIdx.x][3][s]);
        }
        float4 cv = *reinterpret_cast<const float4*>(&d_c[(size_t)bb * H + jj4]);
        float4 cn, hn;
        cn.x = sigmoidf_(Gf.x) * cv.x + sigmoidf_(Gi.x) * tanhf(Gg.x);
        cn.y = sigmoidf_(Gf.y) * cv.y + sigmoidf_(Gi.y) * tanhf(Gg.y);
        cn.z = sigmoidf_(Gf.z) * cv.z + sigmoidf_(Gi.z) * tanhf(Gg.z);
        cn.w = sigmoidf_(Gf.w) * cv.w + sigmoidf_(Gi.w) * tanhf(Gg.w);
        hn.x = sigmoidf_(Go.x) * tanhf(cn.x);
        hn.y = sigmoidf_(Go.y) * tanhf(cn.y);
        hn.z = sigmoidf_(Go.z) * tanhf(cn.z);
        hn.w = sigmoidf_(Go.w) * tanhf(cn.w);
        *reinterpret_cast<float4*>(&d_c[(size_t)bb * H + jj4]) = cn;
        *reinterpret_cast<float4*>(&d_Xcat[(size_t)bb * H4 + K3H + jj4]) = hn;
    }
}

// fused qkv-reduce + attention (R11-proven)
__global__ __launch_bounds__(256) void qkv_attention(const float* __restrict__ ain_b, int t) {
    int b = blockIdx.x;
    __shared__ __align__(16) float sq[H];
    __shared__ float sc[NH][32];

    for (int j4i = threadIdx.x; j4i < K3H / 4; j4i += 256) {
        int j = j4i * 4;
        float4 v = *reinterpret_cast<const float4*>(&ain_b[j]);
#pragma unroll
        for (int s = 0; s < KS_QKV; s++)
            add4(v, *reinterpret_cast<const float4*>(
                &d_qkvp[(size_t)s * B * K3H + (size_t)b * K3H + j]));
        if (j < 1024)
            *reinterpret_cast<float4*>(&sq[j]) = v;
        else if (j < 2048)
            *reinterpret_cast<float4*>(&d_Kc[((size_t)t * B + b) * H + (j - 1024)]) = v;
        else
            *reinterpret_cast<float4*>(&d_Vc[((size_t)t * B + b) * H + (j - 2048)]) = v;
    }
    __syncthreads();

    int w = threadIdx.x >> 5;
    int l = threadIdx.x & 31;
    const float scale = 0.08838834764831845f;  // 1/sqrt(128)

    float4 q4 = *reinterpret_cast<const float4*>(&sq[w * HD + l * 4]);
    for (int s = 0; s <= t; s++) {
        float4 k4 = *reinterpret_cast<const float4*>(&d_Kc[((size_t)s * B + b) * H + w * HD + l * 4]);
        float p = q4.x * k4.x + q4.y * k4.y + q4.z * k4.z + q4.w * k4.w;
#pragma unroll
        for (int off = 16; off; off >>= 1) p += __shfl_xor_sync(0xffffffffu, p, off);
        if (l == 0) sc[w][s] = p * scale;
    }
    __syncwarp();
    float val = (l <= t) ? sc[w][l] : -3.0e38f;
    float mx = val;
#pragma unroll
    for (int off = 16; off; off >>= 1) mx = fmaxf(mx, __shfl_xor_sync(0xffffffffu, mx, off));
    float e = (l <= t) ? expf(val - mx) : 0.f;
    float se = e;
#pragma unroll
    for (int off = 16; off; off >>= 1) se += __shfl_xor_sync(0xffffffffu, se, off);
    float inv = 1.f / se;

    float cx0 = 0.f, cx1 = 0.f, cx2 = 0.f, cx3 = 0.f;
    for (int s = 0; s <= t; s++) {
        float a = __shfl_sync(0xffffffffu, e, s) * inv;
        float4 v4 = *reinterpret_cast<const float4*>(&d_Vc[((size_t)s * B + b) * H + w * HD + l * 4]);
        cx0 = fmaf(a, v4.x, cx0); cx1 = fmaf(a, v4.y, cx1);
        cx2 = fmaf(a, v4.z, cx2); cx3 = fmaf(a, v4.w, cx3);
    }
    float4 o4 = make_float4(cx0, cx1, cx2, cx3);
    *reinterpret_cast<float4*>(&d_ctx[(size_t)b * H + w * HD + l * 4]) = o4;
}

// s-split partial-sum reducer: qin = 0.5*(h + bias + sum partials)  (R12-proven, mode0 only)
__global__ __launch_bounds__(256)
void sum_reduce(const float* __restrict__ P, int ks,
                const float* __restrict__ bias, float* __restrict__ outp) {
    __shared__ __align__(16) float4 red[64][4];
    int tid = blockIdx.x * 256 + threadIdx.x;
    int outIdx = tid >> 2;
    int sg = tid & 3;
    int b = outIdx >> 8;
    int k4 = (outIdx & 255) * 4;
    int per = ks / 4;

    float4 v = (sg == 0) ? *reinterpret_cast<const float4*>(&bias[k4])
                         : make_float4(0.f, 0.f, 0.f, 0.f);
    for (int s = 0; s < per; s++)
        add4(v, *reinterpret_cast<const float4*>(
            &P[(size_t)(sg * per + s) * B * H + (size_t)b * H + k4]));
    red[threadIdx.x >> 2][sg] = v;
    __syncthreads();

    if (threadIdx.x < 64) {
        int o = blockIdx.x * 64 + threadIdx.x;
        int bb = o >> 8;
        int kk = (o & 255) * 4;
        float4 a = red[threadIdx.x][0];
        add4(a, red[threadIdx.x][1]); add4(a, red[threadIdx.x][2]); add4(a, red[threadIdx.x][3]);
        float4 hv = *reinterpret_cast<const float4*>(&d_Xcat[(size_t)bb * H4 + K3H + kk]);
        a.x = 0.5f * (hv.x + a.x); a.y = 0.5f * (hv.y + a.y);
        a.z = 0.5f * (hv.z + a.z); a.w = 0.5f * (hv.w + a.w);
        *reinterpret_cast<float4*>(&outp[(size_t)bb * H + kk]) = a;
    }
}

// fused: qf reduction + logits + top3 + gather. One block per batch row.
__global__ __launch_bounds__(256)
void logits_top3(const float* __restrict__ enc, const float* __restrict__ qt_b,
                 float* __restrict__ out, int t, int out_size) {
    int b = blockIdx.x;
    __shared__ __align__(16) float q[H];
    __shared__ float s[NE];
    __shared__ float sv[96];
    __shared__ int   sn[96];
    __shared__ int   si[3];

    // phase A: q = qt_b + sum of KS_SMALL partials (float4 per thread)
    {
        int k4 = threadIdx.x * 4;
        float4 v = *reinterpret_cast<const float4*>(&qt_b[k4]);
#pragma unroll
        for (int ss = 0; ss < KS_SMALL; ss++)
            add4(v, *reinterpret_cast<const float4*>(
                &d_qp[(size_t)ss * B * H + (size_t)b * H + k4]));
        *reinterpret_cast<float4*>(&q[k4]) = v;
    }
    __syncthreads();

    // phase B: logits; warp w handles n = w*64 .. +63 (identical dot order to prior rounds)
    int w = threadIdx.x >> 5, l = threadIdx.x & 31;
    for (int ni = 0; ni < 64; ni++) {
        int n = w * 64 + ni;
        const float4* e4 = reinterpret_cast<const float4*>(&enc[((size_t)b * NE + n) * H]);
        float acc = 0.f;
#pragma unroll
        for (int r = 0; r < 8; r++) {
            float4 ev = e4[l + r * 32];
            float4 qv = *reinterpret_cast<const float4*>(&q[(l + r * 32) * 4]);
            acc += ev.x * qv.x + ev.y * qv.y + ev.z * qv.z + ev.w * qv.w;
        }
#pragma unroll
        for (int off = 16; off; off >>= 1) acc += __shfl_xor_sync(0xffffffffu, acc, off);
        if (l == 0) {
            s[n] = acc;
            out[(size_t)t * B * NE + (size_t)b * NE + n] = acc;
        }
    }
    __syncthreads();

    // phase C: top3 (warp 0 lanes scan 16 each, merge)
    if (threadIdx.x < 32) {
        int ll = threadIdx.x;
        float v0 = -3.0e38f, v1 = -3.0e38f, v2 = -3.0e38f;
        int i0 = 0, i1 = 0, i2 = 0;
        for (int k = 0; k < 16; k++) {
            int n = ll * 16 + k;
            float v = s[n];
            if (v > v0)      { v2 = v1; i2 = i1; v1 = v0; i1 = i0; v0 = v; i0 = n; }
            else if (v > v1) { v2 = v1; i2 = i1; v1 = v; i1 = n; }
            else if (v > v2) { v2 = v; i2 = n; }
        }
        sv[ll * 3 + 0] = v0; sn[ll * 3 + 0] = i0;
        sv[ll * 3 + 1] = v1; sn[ll * 3 + 1] = i1;
        sv[ll * 3 + 2] = v2; sn[ll * 3 + 2] = i2;
    }
    __syncthreads();
    if (threadIdx.x == 0) {
        float v0 = -3.0e38f, v1 = -3.0e38f, v2 = -3.0e38f;
        int i0 = 0, i1 = 0, i2 = 0;
        for (int k = 0; k < 96; k++) {
            float v = sv[k]; int n = sn[k];
            bool b0 = (v > v0) || (v == v0 && n < i0);
            bool b1 = (v > v1) || (v == v1 && n < i1);
            bool b2 = (v > v2) || (v == v2 && n < i2);
            if (b0)      { v2 = v1; i2 = i1; v1 = v0; i1 = i0; v0 = v; i0 = n; }
            else if (b1) { v2 = v1; i2 = i1; v1 = v; i1 = n; }
            else if (b2) { v2 = v; i2 = n; }
        }
        int a0 = i0, a1 = i1, a2 = i2, tmp;
        if (a0 > a1) { tmp = a0; a0 = a1; a1 = tmp; }
        if (a1 > a2) { tmp = a1; a1 = a2; a2 = tmp; }
        if (a0 > a1) { tmp = a0; a0 = a1; a1 = tmp; }
        si[0] = a0; si[1] = a1; si[2] = a2;
        if (out_size >= LOGITS_TOT + IDX_TOT) {
            float* op = out + (size_t)LOGITS_TOT + (size_t)t * B * 3 + (size_t)b * 3;
            op[0] = (float)a0; op[1] = (float)a1; op[2] = (float)a2;
        }
    }
    __syncthreads();

    // phase D: gather top3 rows into x
    for (int r = 0; r < 3; r++) {
        const float4* src = reinterpret_cast<const float4*>(&enc[((size_t)b * NE + si[r]) * H]);
        float4* dst = reinterpret_cast<float4*>(&d_Xcat[(size_t)b * H4 + r * H]);
        for (int k = threadIdx.x; k < 256; k += 256) dst[k] = src[k];
    }
}

// ---------------- launch ----------------
extern "C" void kernel_launch(void* const* d_in, const int* in_sizes, int n_in,
                              void* d_out, int out_size) {
    const float* enc     = (const float*)d_in[0];
    const float* hidden  = (const float*)d_in[1];
    const float* cell    = (const float*)d_in[2];
    const float* init_in = (const float*)d_in[4];
    int base = (in_sizes[5] > 1000) ? 5 : 6;   // skip scalar max_steps if present
    const float* W_ih   = (const float*)d_in[base + 0];
    const float* b_ih   = (const float*)d_in[base + 1];
    const float* W_hh   = (const float*)d_in[base + 2];
    const float* b_hh   = (const float*)d_in[base + 3];
    const float* ain_w  = (const float*)d_in[base + 4];
    const float* ain_b  = (const float*)d_in[base + 5];
    const float* aout_w = (const float*)d_in[base + 6];
    const float* aout_b = (const float*)d_in[base + 7];
    const float* qt_w   = (const float*)d_in[base + 8];
    const float* qt_b   = (const float*)d_in[base + 9];
    float* out = (float*)d_out;

    float *pW, *pX, *pGates, *pQkv, *pCtx, *pAop, *pQin, *pQp;
    cudaGetSymbolAddress((void**)&pW,    d_Wcat);
    cudaGetSymbolAddress((void**)&pX,    d_Xcat);
    cudaGetSymbolAddress((void**)&pGates,d_gatesp);
    cudaGetSymbolAddress((void**)&pQkv,  d_qkvp);
    cudaGetSymbolAddress((void**)&pCtx,  d_ctx);
    cudaGetSymbolAddress((void**)&pAop,  d_aop);
    cudaGetSymbolAddress((void**)&pQin,  d_qin);
    cudaGetSymbolAddress((void**)&pQp,   d_qp);

    init_wcat<<<65536, 256>>>(W_ih, W_hh);
    init_state<<<1024, 256>>>(hidden, cell, init_in);

    for (int t = 0; t < SQ; t++) {
        // LSTM gates: [64,4096] = Xcat @ Wcat^T; 16 n-blocks x KS 16 -> 256 CTAs
        gemm64<<<dim3(16, KS_GATES), 128>>>(pX, H4, pW, H4, H4, pGates, H4 / KS_GATES);
        lstm_update<<<256, 256>>>(b_ih, b_hh);
        // QKV: [64,3072] = h @ ain_w^T; 12 x 16 -> 192 CTAs
        gemm64<<<dim3(12, KS_QKV), 128>>>(pX + K3H, H4, ain_w, H, K3H, pQkv, H / KS_QKV);
        qkv_attention<<<64, 256>>>(ain_b, t);
        // attn_out: [64,1024] = ctx @ aout_w^T; 4 x 32 -> 128 CTAs
        gemm64<<<dim3(4, KS_SMALL), 128>>>(pCtx, H, aout_w, H, H, pAop, H / KS_SMALL);
        sum_reduce<<<256, 256>>>(pAop, KS_SMALL, aout_b, pQin);
        // query: [64,1024] = qin @ qt_w^T; 4 x 32 -> 128 CTAs
        gemm64<<<dim3(4, KS_SMALL), 128>>>(pQin, H, qt_w, H, H, pQp, H / KS_SMALL);
        // fused qf-reduce + logits + top3 + gather
        logits_top3<<<64, 256>>>(enc, qt_b, out, t, out_size);
    }
}

// round 15
// speedup vs baseline: 1.2887x; 1.2887x over previous
#include <cuda_runtime.h>
#include <math.h>

#define B    64
#define H    1024
#define NH   8
#define HD   128
#define SQ   24
#define NE   512
#define K3H  3072
#define H4   4096

#define LOGITS_TOT (SQ*B*NE)   // 786432
#define IDX_TOT    (SQ*B*3)    // 4608

#define KS_GATES 16
#define KS_QKV   16
#define KS_SMALL 32

typedef unsigned long long ull;

// ---------------- persistent device scratch (no allocations allowed) ----------------
__device__ float d_Wcat[(size_t)H4 * H4];     // [4096][4096] = W_ih | W_hh packed
__device__ float d_Xcat[(size_t)B * H4];      // [64][4096]  = x(3072) | h(1024)
__device__ float d_c[(size_t)B * H];
__device__ float d_gatesp[KS_GATES * (size_t)B * H4];
__device__ float d_qkvp[KS_QKV * (size_t)B * K3H];
__device__ float d_q[(size_t)B * H];
__device__ float d_Kc[(size_t)SQ * B * H];
__device__ float d_Vc[(size_t)SQ * B * H];
__device__ float d_ctx[(size_t)B * H];
__device__ float d_aop[KS_SMALL * (size_t)B * H];
__device__ float d_qin[(size_t)B * H];
__device__ float d_qp[KS_SMALL * (size_t)B * H];
__device__ float d_qf[(size_t)B * H];

// ---------------- packed f32x2 helpers ----------------
__device__ __forceinline__ ull pk2(float x, float y) {
    ull r;
    asm("mov.b64 %0, {%1,%2};" : "=l"(r) : "f"(x), "f"(y));
    return r;
}
__device__ __forceinline__ void fma2(ull& d, ull a, ull b) {
    asm("fma.rn.f32x2 %0, %1, %2, %3;" : "=l"(d) : "l"(a), "l"(b), "l"(d));
}
__device__ __forceinline__ float2 up2(ull v) {
    float2 r;
    asm("mov.b64 {%0,%1}, %2;" : "=f"(r.x), "=f"(r.y) : "l"(v));
    return r;
}
__device__ __forceinline__ void add4(float4& a, float4 b) {
    a.x += b.x; a.y += b.y; a.z += b.z; a.w += b.w;
}
// streaming load (ld.global.cs) — evict-early, keeps weights resident in L2
__device__ __forceinline__ float4 ld4_stream(const float* p) {
    return __ldcs(reinterpret_cast<const float4*>(p));
}

// ---------------- init kernels ----------------
__global__ void init_wcat(const float* __restrict__ W_ih, const float* __restrict__ W_hh) {
    size_t id = (size_t)blockIdx.x * 256 + threadIdx.x;
    int j = (int)(id >> 12);
    int k = (int)(id & 4095);
    d_Wcat[id] = (k < K3H) ? W_ih[(size_t)j * K3H + k]
                           : W_hh[(size_t)j * H + (k - K3H)];
}

__global__ void init_state(const float* __restrict__ hidden,
                           const float* __restrict__ cell,
                           const float* __restrict__ init_in) {
    int id = blockIdx.x * 256 + threadIdx.x;
    int b = id >> 12;
    int k = id & 4095;
    if (k < K3H) {
        d_Xcat[id] = init_in[(size_t)b * K3H + k];
    } else {
        d_Xcat[id] = hidden[(size_t)b * H + (k - K3H)];
        d_c[(size_t)b * H + (k - K3H)] = cell[(size_t)b * H + (k - K3H)];
    }
}

// ---------------- fp32 GEMM with packed FFMA2 (R7-proven, unchanged) ----------------
__global__ __launch_bounds__(128)
void gemm64(const float* __restrict__ A, int lda,
            const float* __restrict__ W, int K, int N,
            float* __restrict__ C, int kper)
{
    __shared__ __align__(16) float As[2][16][72];
    __shared__ __align__(16) float Ws[2][16][260];

    const int tx = threadIdx.x;
    const int tm = tx >> 4;
    const int tn = tx & 15;
    const int nblk = blockIdx.x * 256;
    const int k0 = blockIdx.y * kper;

    const int ldRow = tx >> 2;
    const int ldKg  = tx & 3;

    const float* Aptr = A + (size_t)ldRow * lda + k0 + ldKg * 4;
    const float* Wptr = W + (size_t)(nblk + ldRow) * K + k0 + ldKg * 4;

    ull acc[8][8];
#pragma unroll
    for (int i = 0; i < 8; i++)
#pragma unroll
        for (int j = 0; j < 8; j++) acc[i][j] = 0ull;

    const int nk = kper / 16;

    {
#pragma unroll
        for (int i = 0; i < 2; i++) {
            float4 v = *reinterpret_cast<const float4*>(Aptr + (size_t)i * 32 * lda);
            int row = ldRow + i * 32;
            As[0][ldKg * 4 + 0][row] = v.x; As[0][ldKg * 4 + 1][row] = v.y;
            As[0][ldKg * 4 + 2][row] = v.z; As[0][ldKg * 4 + 3][row] = v.w;
        }
#pragma unroll
        for (int i = 0; i < 8; i++) {
            float4 v = *reinterpret_cast<const float4*>(Wptr + (size_t)i * 32 * K);
            int row = ldRow + i * 32;
            Ws[0][ldKg * 4 + 0][row] = v.x; Ws[0][ldKg * 4 + 1][row] = v.y;
            Ws[0][ldKg * 4 + 2][row] = v.z; Ws[0][ldKg * 4 + 3][row] = v.w;
        }
    }
    __syncthreads();

    for (int it = 0; it < nk; it++) {
        const int st = it & 1;
        float4 va[2], vw[8];
        if (it + 1 < nk) {
            const int koff = (it + 1) * 16;
#pragma unroll
            for (int i = 0; i < 2; i++)
                va[i] = *reinterpret_cast<const float4*>(Aptr + (size_t)i * 32 * lda + koff);
#pragma unroll
            for (int i = 0; i < 8; i++)
                vw[i] = *reinterpret_cast<const float4*>(Wptr + (size_t)i * 32 * K + koff);
        }
#pragma unroll
        for (int kk = 0; kk < 16; kk++) {
            float a[8];
            *reinterpret_cast<float4*>(&a[0]) = *reinterpret_cast<const float4*>(&As[st][kk][tm * 8]);
            *reinterpret_cast<float4*>(&a[4]) = *reinterpret_cast<const float4*>(&As[st][kk][tm * 8 + 4]);
            ull ap[8];
#pragma unroll
            for (int i = 0; i < 8; i++) ap[i] = pk2(a[i], a[i]);
#pragma unroll
            for (int q = 0; q < 4; q++) {
                const ull* bp = reinterpret_cast<const ull*>(&Ws[st][kk][q * 64 + tn * 4]);
                ull b0 = bp[0], b1 = bp[1];
#pragma unroll
                for (int i = 0; i < 8; i++) {
                    fma2(acc[i][q * 2 + 0], ap[i], b0);
                    fma2(acc[i][q * 2 + 1], ap[i], b1);
                }
            }
        }
        if (it + 1 < nk) {
            const int sn = st ^ 1;
#pragma unroll
            for (int i = 0; i < 2; i++) {
                int row = ldRow + i * 32;
                As[sn][ldKg * 4 + 0][row] = va[i].x; As[sn][ldKg * 4 + 1][row] = va[i].y;
                As[sn][ldKg * 4 + 2][row] = va[i].z; As[sn][ldKg * 4 + 3][row] = va[i].w;
            }
#pragma unroll
            for (int i = 0; i < 8; i++) {
                int row = ldRow + i * 32;
                Ws[sn][ldKg * 4 + 0][row] = vw[i].x; Ws[sn][ldKg * 4 + 1][row] = vw[i].y;
                Ws[sn][ldKg * 4 + 2][row] = vw[i].z; Ws[sn][ldKg * 4 + 3][row] = vw[i].w;
            }
        }
        __syncthreads();
    }

    float* Cp = C + (size_t)blockIdx.y * B * N;
#pragma unroll
    for (int i = 0; i < 8; i++) {
        const size_t rbase = (size_t)(tm * 8 + i) * N + nblk;
#pragma unroll
        for (int q = 0; q < 4; q++) {
            float2 lo = up2(acc[i][q * 2 + 0]);
            float2 hi = up2(acc[i][q * 2 + 1]);
            float4 v = make_float4(lo.x, lo.y, hi.x, hi.y);
            *reinterpret_cast<float4*>(&Cp[rbase + q * 64 + tn * 4]) = v;
        }
    }
}

// ---------------- reductions (R12-proven) ----------------
__device__ __forceinline__ float sigmoidf_(float x) { return 1.f / (1.f + expf(-x)); }

__global__ __launch_bounds__(256)
void lstm_update(const float* __restrict__ b_ih, const float* __restrict__ b_hh) {
    __shared__ __align__(16) float4 red[64][4][4];
    int tid = blockIdx.x * 256 + threadIdx.x;
    int outIdx = tid >> 2;
    int sg = tid & 3;
    int b = outIdx >> 8;
    int j4 = (outIdx & 255) * 4;
    size_t base = (size_t)b * H4;

    float4 gi, gf, gg, go;
    if (sg == 0) {
        gi = *reinterpret_cast<const float4*>(&b_ih[j4]);
        gf = *reinterpret_cast<const float4*>(&b_ih[1024 + j4]);
        gg = *reinterpret_cast<const float4*>(&b_ih[2048 + j4]);
        go = *reinterpret_cast<const float4*>(&b_ih[3072 + j4]);
        add4(gi, *reinterpret_cast<const float4*>(&b_hh[j4]));
        add4(gf, *reinterpret_cast<const float4*>(&b_hh[1024 + j4]));
        add4(gg, *reinterpret_cast<const float4*>(&b_hh[2048 + j4]));
        add4(go, *reinterpret_cast<const float4*>(&b_hh[3072 + j4]));
    } else {
        gi = gf = gg = go = make_float4(0.f, 0.f, 0.f, 0.f);
    }
#pragma unroll
    for (int s = 0; s < 4; s++) {
        const float* g = d_gatesp + (size_t)(sg * 4 + s) * B * H4 + base;
        add4(gi, *reinterpret_cast<const float4*>(&g[j4]));
        add4(gf, *reinterpret_cast<const float4*>(&g[1024 + j4]));
        add4(gg, *reinterpret_cast<const float4*>(&g[2048 + j4]));
        add4(go, *reinterpret_cast<const float4*>(&g[3072 + j4]));
    }
    int lo = threadIdx.x >> 2;
    red[lo][0][sg] = gi; red[lo][1][sg] = gf;
    red[lo][2][sg] = gg; red[lo][3][sg] = go;
    __syncthreads();

    if (threadIdx.x < 64) {
        int o = blockIdx.x * 64 + threadIdx.x;
        int bb = o >> 8;
        int jj4 = (o & 255) * 4;
        float4 Gi = red[threadIdx.x][0][0], Gf = red[threadIdx.x][1][0];
        float4 Gg = red[threadIdx.x][2][0], Go = red[threadIdx.x][3][0];
#pragma unroll
        for (int s = 1; s < 4; s++) {
            add4(Gi, red[threadIdx.x][0][s]); add4(Gf, red[threadIdx.x][1][s]);
            add4(Gg, red[threadIdx.x][2][s]); add4(Go, red[threadIdx.x][3][s]);
        }
        float4 cv = *reinterpret_cast<const float4*>(&d_c[(size_t)bb * H + jj4]);
        float4 cn, hn;
        cn.x = sigmoidf_(Gf.x) * cv.x + sigmoidf_(Gi.x) * tanhf(Gg.x);
        cn.y = sigmoidf_(Gf.y) * cv.y + sigmoidf_(Gi.y) * tanhf(Gg.y);
        cn.z = sigmoidf_(Gf.z) * cv.z + sigmoidf_(Gi.z) * tanhf(Gg.z);
        cn.w = sigmoidf_(Gf.w) * cv.w + sigmoidf_(Gi.w) * tanhf(Gg.w);
        hn.x = sigmoidf_(Go.x) * tanhf(cn.x);
        hn.y = sigmoidf_(Go.y) * tanhf(cn.y);
        hn.z = sigmoidf_(Go.z) * tanhf(cn.z);
        hn.w = sigmoidf_(Go.w) * tanhf(cn.w);
        *reinterpret_cast<float4*>(&d_c[(size_t)bb * H + jj4]) = cn;
        *reinterpret_cast<float4*>(&d_Xcat[(size_t)bb * H4 + K3H + jj4]) = hn;
    }
}

__global__ __launch_bounds__(256)
void qkv_reduce(const float* __restrict__ ain_b, int t) {
    __shared__ __align__(16) float4 red[64][4];
    int tid = blockIdx.x * 256 + threadIdx.x;
    int outIdx = tid >> 2;
    int sg = tid & 3;
    int b = outIdx / 768;
    int j4 = (outIdx - b * 768) * 4;

    float4 v = (sg == 0) ? *reinterpret_cast<const float4*>(&ain_b[j4])
                         : make_float4(0.f, 0.f, 0.f, 0.f);
#pragma unroll
    for (int s = 0; s < 4; s++)
        add4(v, *reinterpret_cast<const float4*>(
            &d_qkvp[(size_t)(sg * 4 + s) * B * K3H + (size_t)b * K3H + j4]));
    red[threadIdx.x >> 2][sg] = v;
    __syncthreads();

    if (threadIdx.x < 64) {
        int o = blockIdx.x * 64 + threadIdx.x;
        int bb = o / 768;
        int jj = (o - bb * 768) * 4;
        float4 a = red[threadIdx.x][0];
        add4(a, red[threadIdx.x][1]); add4(a, red[threadIdx.x][2]); add4(a, red[threadIdx.x][3]);
        if (jj < 1024)
            *reinterpret_cast<float4*>(&d_q[(size_t)bb * H + jj]) = a;
        else if (jj < 2048)
            *reinterpret_cast<float4*>(&d_Kc[((size_t)t * B + bb) * H + (jj - 1024)]) = a;
        else
            *reinterpret_cast<float4*>(&d_Vc[((size_t)t * B + bb) * H + (jj - 2048)]) = a;
    }
}

__global__ __launch_bounds__(256) void attention_kernel(int t) {
    int b = blockIdx.x;
    __shared__ __align__(16) float sq[H];
    __shared__ float sc[NH][32];
    {
        int k4 = threadIdx.x * 4;
        *reinterpret_cast<float4*>(&sq[k4]) =
            *reinterpret_cast<const float4*>(&d_q[(size_t)b * H + k4]);
    }
    __syncthreads();

    int w = threadIdx.x >> 5;
    int l = threadIdx.x & 31;
    const float scale = 0.08838834764831845f;

    float4 q4 = *reinterpret_cast<const float4*>(&sq[w * HD + l * 4]);
    for (int s = 0; s <= t; s++) {
        float4 k4 = *reinterpret_cast<const float4*>(&d_Kc[((size_t)s * B + b) * H + w * HD + l * 4]);
        float p = q4.x * k4.x + q4.y * k4.y + q4.z * k4.z + q4.w * k4.w;
#pragma unroll
        for (int off = 16; off; off >>= 1) p += __shfl_xor_sync(0xffffffffu, p, off);
        if (l == 0) sc[w][s] = p * scale;
    }
    __syncwarp();
    float val = (l <= t) ? sc[w][l] : -3.0e38f;
    float mx = val;
#pragma unroll
    for (int off = 16; off; off >>= 1) mx = fmaxf(mx, __shfl_xor_sync(0xffffffffu, mx, off));
    float e = (l <= t) ? expf(val - mx) : 0.f;
    float se = e;
#pragma unroll
    for (int off = 16; off; off >>= 1) se += __shfl_xor_sync(0xffffffffu, se, off);
    float inv = 1.f / se;

    float cx0 = 0.f, cx1 = 0.f, cx2 = 0.f, cx3 = 0.f;
    for (int s = 0; s <= t; s++) {
        float a = __shfl_sync(0xffffffffu, e, s) * inv;
        float4 v4 = *reinterpret_cast<const float4*>(&d_Vc[((size_t)s * B + b) * H + w * HD + l * 4]);
        cx0 = fmaf(a, v4.x, cx0); cx1 = fmaf(a, v4.y, cx1);
        cx2 = fmaf(a, v4.z, cx2); cx3 = fmaf(a, v4.w, cx3);
    }
    float4 o4 = make_float4(cx0, cx1, cx2, cx3);
    *reinterpret_cast<float4*>(&d_ctx[(size_t)b * H + w * HD + l * 4]) = o4;
}

// mode 0: qin = 0.5*(h + sum)   mode 1: qf = sum
__global__ __launch_bounds__(256)
void sum_reduce(const float* __restrict__ P, int ks,
                const float* __restrict__ bias, float* __restrict__ outp, int mode) {
    __shared__ __align__(16) float4 red[64][4];
    int tid = blockIdx.x * 256 + threadIdx.x;
    int outIdx = tid >> 2;
    int sg = tid & 3;
    int b = outIdx >> 8;
    int k4 = (outIdx & 255) * 4;
    int per = ks / 4;

    float4 v = (sg == 0) ? *reinterpret_cast<const float4*>(&bias[k4])
                         : make_float4(0.f, 0.f, 0.f, 0.f);
    for (int s = 0; s < per; s++)
        add4(v, *reinterpret_cast<const float4*>(
            &P[(size_t)(sg * per + s) * B * H + (size_t)b * H + k4]));
    red[threadIdx.x >> 2][sg] = v;
    __syncthreads();

    if (threadIdx.x < 64) {
        int o = blockIdx.x * 64 + threadIdx.x;
        int bb = o >> 8;
        int kk = (o & 255) * 4;
        float4 a = red[threadIdx.x][0];
        add4(a, red[threadIdx.x][1]); add4(a, red[threadIdx.x][2]); add4(a, red[threadIdx.x][3]);
        if (mode == 0) {
            float4 hv = *reinterpret_cast<const float4*>(&d_Xcat[(size_t)bb * H4 + K3H + kk]);
            a.x = 0.5f * (hv.x + a.x); a.y = 0.5f * (hv.y + a.y);
            a.z = 0.5f * (hv.z + a.z); a.w = 0.5f * (hv.w + a.w);
        }
        *reinterpret_cast<float4*>(&outp[(size_t)bb * H + kk]) = a;
    }
}

__global__ __launch_bounds__(256)
void logits_kernel(const float* __restrict__ enc, float* __restrict__ out, int t) {
    int b = blockIdx.x, ch = blockIdx.y;
    __shared__ __align__(16) float q[H];
    {
        int k4 = threadIdx.x * 4;
        *reinterpret_cast<float4*>(&q[k4]) =
            *reinterpret_cast<const float4*>(&d_qf[(size_t)b * H + k4]);
    }
    __syncthreads();
    int w = threadIdx.x >> 5, l = threadIdx.x & 31;
    for (int ni = 0; ni < 16; ni++) {
        int n = ch * 128 + w * 16 + ni;
        const float* erow = &enc[((size_t)b * NE + n) * H];
        float acc = 0.f;
#pragma unroll
        for (int r = 0; r < 8; r++) {
            float4 ev = ld4_stream(erow + (l + r * 32) * 4);   // streaming: keep weights in L2
            float4 qv = *reinterpret_cast<const float4*>(&q[(l + r * 32) * 4]);
            acc += ev.x * qv.x + ev.y * qv.y + ev.z * qv.z + ev.w * qv.w;
        }
#pragma unroll
        for (int off = 16; off; off >>= 1) acc += __shfl_xor_sync(0xffffffffu, acc, off);
        if (l == 0) out[(size_t)t * B * NE + (size_t)b * NE + n] = acc;
    }
}

__global__ __launch_bounds__(128)
void top3_kernel(const float* __restrict__ enc, float* __restrict__ out, int t, int out_size) {
    int b = blockIdx.x;
    __shared__ float sv[96];
    __shared__ int   sn[96];
    __shared__ int   si[3];
    const float* lg = out + (size_t)t * B * NE + (size_t)b * NE;

    if (threadIdx.x < 32) {
        int l = threadIdx.x;
        float v0 = -3.0e38f, v1 = -3.0e38f, v2 = -3.0e38f;
        int i0 = 0, i1 = 0, i2 = 0;
        for (int k = 0; k < 16; k++) {
            int n = l * 16 + k;
            float v = lg[n];
            if (v > v0)      { v2 = v1; i2 = i1; v1 = v0; i1 = i0; v0 = v; i0 = n; }
            else if (v > v1) { v2 = v1; i2 = i1; v1 = v; i1 = n; }
            else if (v > v2) { v2 = v; i2 = n; }
        }
        sv[l * 3 + 0] = v0; sn[l * 3 + 0] = i0;
        sv[l * 3 + 1] = v1; sn[l * 3 + 1] = i1;
        sv[l * 3 + 2] = v2; sn[l * 3 + 2] = i2;
    }
    __syncthreads();
    if (threadIdx.x == 0) {
        float v0 = -3.0e38f, v1 = -3.0e38f, v2 = -3.0e38f;
        int i0 = 0, i1 = 0, i2 = 0;
        for (int k = 0; k < 96; k++) {
            float v = sv[k]; int n = sn[k];
            bool b0 = (v > v0) || (v == v0 && n < i0);
            bool b1 = (v > v1) || (v == v1 && n < i1);
            bool b2 = (v > v2) || (v == v2 && n < i2);
            if (b0)      { v2 = v1; i2 = i1; v1 = v0; i1 = i0; v0 = v; i0 = n; }
            else if (b1) { v2 = v1; i2 = i1; v1 = v; i1 = n; }
            else if (b2) { v2 = v; i2 = n; }
        }
        int a0 = i0, a1 = i1, a2 = i2, tmp;
        if (a0 > a1) { tmp = a0; a0 = a1; a1 = tmp; }
        if (a1 > a2) { tmp = a1; a1 = a2; a2 = tmp; }
        if (a0 > a1) { tmp = a0; a0 = a1; a1 = tmp; }
        si[0] = a0; si[1] = a1; si[2] = a2;
        if (out_size >= LOGITS_TOT + IDX_TOT) {
            float* op = out + (size_t)LOGITS_TOT + (size_t)t * B * 3 + (size_t)b * 3;
            op[0] = (float)a0; op[1] = (float)a1; op[2] = (float)a2;
        }
    }
    __syncthreads();
    for (int r = 0; r < 3; r++) {
        const float* src = &enc[((size_t)b * NE + si[r]) * H];
        float4* dst = reinterpret_cast<float4*>(&d_Xcat[(size_t)b * H4 + r * H]);
        for (int k = threadIdx.x; k < 256; k += 128) dst[k] = ld4_stream(src + k * 4);
    }
}

// ---------------- launch ----------------
extern "C" void kernel_launch(void* const* d_in, const int* in_sizes, int n_in,
                              void* d_out, int out_size) {
    const float* enc     = (const float*)d_in[0];
    const float* hidden  = (const float*)d_in[1];
    const float* cell    = (const float*)d_in[2];
    const float* init_in = (const float*)d_in[4];
    int base = (in_sizes[5] > 1000) ? 5 : 6;   // skip scalar max_steps if present
    const float* W_ih   = (const float*)d_in[base + 0];
    const float* b_ih   = (const float*)d_in[base + 1];
    const float* W_hh   = (const float*)d_in[base + 2];
    const float* b_hh   = (const float*)d_in[base + 3];
    const float* ain_w  = (const float*)d_in[base + 4];
    const float* ain_b  = (const float*)d_in[base + 5];
    const float* aout_w = (const float*)d_in[base + 6];
    const float* aout_b = (const float*)d_in[base + 7];
    const float* qt_w   = (const float*)d_in[base + 8];
    const float* qt_b   = (const float*)d_in[base + 9];
    float* out = (float*)d_out;

    float *pW, *pX, *pGates, *pQkv, *pCtx, *pAop, *pQin, *pQp, *pQf;
    cudaGetSymbolAddress((void**)&pW,    d_Wcat);
    cudaGetSymbolAddress((void**)&pX,    d_Xcat);
    cudaGetSymbolAddress((void**)&pGates,d_gatesp);
    cudaGetSymbolAddress((void**)&pQkv,  d_qkvp);
    cudaGetSymbolAddress((void**)&pCtx,  d_ctx);
    cudaGetSymbolAddress((void**)&pAop,  d_aop);
    cudaGetSymbolAddress((void**)&pQin,  d_qin);
    cudaGetSymbolAddress((void**)&pQp,   d_qp);
    cudaGetSymbolAddress((void**)&pQf,   d_qf);

    init_wcat<<<65536, 256>>>(W_ih, W_hh);
    init_state<<<1024, 256>>>(hidden, cell, init_in);

    for (int t = 0; t < SQ; t++) {
        // LSTM gates: [64,4096] = Xcat @ Wcat^T; 16 n-blocks x KS 16 -> 256 CTAs
        gemm64<<<dim3(16, KS_GATES), 128>>>(pX, H4, pW, H4, H4, pGates, H4 / KS_GATES);
        lstm_update<<<256, 256>>>(b_ih, b_hh);
        // QKV: [64,3072] = h @ ain_w^T; 12 x 16 -> 192 CTAs
        gemm64<<<dim3(12, KS_QKV), 128>>>(pX + K3H, H4, ain_w, H, K3H, pQkv, H / KS_QKV);
        qkv_reduce<<<768, 256>>>(ain_b, t);
        attention_kernel<<<64, 256>>>(t);
        // attn_out: [64,1024] = ctx @ aout_w^T; 4 x 32 -> 128 CTAs
        gemm64<<<dim3(4, KS_SMALL), 128>>>(pCtx, H, aout_w, H, H, pAop, H / KS_SMALL);
        sum_reduce<<<256, 256>>>(pAop, KS_SMALL, aout_b, pQin, 0);
        // query: [64,1024] = qin @ qt_w^T; 4 x 32 -> 128 CTAs
        gemm64<<<dim3(4, KS_SMALL), 128>>>(pQin, H, qt_w, H, H, pQp, H / KS_SMALL);
        sum_reduce<<<256, 256>>>(pQp, KS_SMALL, qt_b, pQf, 1);
        logits_kernel<<<dim3(64, 4), 256>>>(enc, out, t);
        top3_kernel<<<64, 128>>>(enc, out, t, out_size);
    }
}